// round 14
// baseline (speedup 1.0000x reference)
#include <cuda_runtime.h>
#include <cstdint>

// Problem constants (fixed by setup_inputs): B=96, N_NODE=512, D=128, n_steps=5
#define NB 96
#define NN 512
#define ND 128
#define NROWS (NB * NN)            // 49152
#define NSTEPS 5

// Scratch (allocation-free rule: __device__ globals)
// g_W2: weights pair-packed: [w][k2][c][2] with value = W[c][2*k2+p]
__device__ float g_W2[7 * ND * ND];
// g_hp: pair-packed over node j: element (b, j, f) at ((b*256 + j/2)*256 + f*2 + (j&1))
__device__ float g_hp[(size_t)NB * 256 * 256];
__device__ float g_neigh[(size_t)NROWS * ND];   // normal [node][feat]
// weight order: 0=Wz 1=Uz 2=Wr 3=Ur 4=Wh 5=Uh 6=Wp

typedef unsigned long long ull;

__device__ __forceinline__ void fma2(ull& d, ull a, ull b) {
    asm("fma.rn.f32x2 %0, %1, %2, %0;" : "+l"(d) : "l"(a), "l"(b));
}
__device__ __forceinline__ void unpack2(ull v, float& lo, float& hi) {
    asm("mov.b64 {%0,%1}, %2;" : "=f"(lo), "=f"(hi) : "l"(v));
}
__device__ __forceinline__ float accval(ull v) {
    float lo, hi; unpack2(v, lo, hi); return lo + hi;
}
__device__ __forceinline__ float sigmoidf_(float x) { return 1.0f / (1.0f + __expf(-x)); }
__device__ __forceinline__ uint32_t s2u(const void* p) {
    uint32_t a;
    asm("{ .reg .u64 t; cvta.to.shared.u64 t, %1; cvt.u32.u64 %0, t; }" : "=r"(a) : "l"(p));
    return a;
}
__device__ __forceinline__ void cp16(float* dst, const float* src) {
    asm volatile("cp.async.cg.shared.global [%0], [%1], 16;" :: "r"(s2u(dst)), "l"(src));
}
#define CP_COMMIT() asm volatile("cp.async.commit_group;")
#define CP_WAIT(n)  asm volatile("cp.async.wait_group %0;" :: "n"(n))

// ---------------------------------------------------------------------------
// Warp tiling: 8 warps = 2 row-groups x 4 col-groups; warp tile 32r x 32c.
// lane = lr*4 + lc (lr = lane>>2 in 0..7, lc = lane&3).
// Thread: 4 rows (r0 = warpR*32 + lr*4), 8 cols = 4 adjacent col-pairs at
// pair index cp = warpC*16 + lc + 4g (g=0..3); col = 2*cp + (j&1), j = 2g+(0|1).
// W per load: one ulonglong2 covers both cols of a pair (k-even, k-odd each).
// Wavefronts: W-load = 4 lc x 16B = 64B (1 wf); A-load = 8 lr x 16B rotated
// by LDA padding (1 wf).
// ---------------------------------------------------------------------------
__device__ __forceinline__ int col_of(int warpC, int lc, int j) {
    return 2 * (warpC * 16 + lc + 4 * (j >> 1)) + (j & 1);
}

// K-paired micro-kernel over 64 k (sW holds 32 k2-rows of 256 floats).
// sX rows at kbase float-offset. acc[i][j] = f32x2 (even-k, odd-k) partials.
template <int LDA>
__device__ __forceinline__ void mma_w(const float* __restrict__ sX,
                                      const float* __restrict__ sW,
                                      int kbase, int r0, int lc, int warpC,
                                      ull acc[4][8]) {
    const float* wbase = sW + 4 * (warpC * 16 + lc);
#pragma unroll 2
    for (int kq = 0; kq < 16; kq++) {
        ulonglong2 av[4];
#pragma unroll
        for (int i = 0; i < 4; i++)
            av[i] = *(const ulonglong2*)(sX + (r0 + i) * LDA + kbase + kq * 4);
#pragma unroll
        for (int h = 0; h < 2; h++) {
            const float* wr = wbase + (kq * 2 + h) * 256;
            ulonglong2 w0 = *(const ulonglong2*)(wr);
            ulonglong2 w1 = *(const ulonglong2*)(wr + 16);
            ulonglong2 w2 = *(const ulonglong2*)(wr + 32);
            ulonglong2 w3 = *(const ulonglong2*)(wr + 48);
#pragma unroll
            for (int i = 0; i < 4; i++) {
                ull ap = h ? av[i].y : av[i].x;
                fma2(acc[i][0], ap, w0.x); fma2(acc[i][1], ap, w0.y);
                fma2(acc[i][2], ap, w1.x); fma2(acc[i][3], ap, w1.y);
                fma2(acc[i][4], ap, w2.x); fma2(acc[i][5], ap, w2.y);
                fma2(acc[i][6], ap, w3.x); fma2(acc[i][7], ap, w3.y);
            }
        }
    }
}
__device__ __forceinline__ void zacc(ull acc[4][8]) {
#pragma unroll
    for (int i = 0; i < 4; i++)
#pragma unroll
        for (int j = 0; j < 8; j++) acc[i][j] = 0ull;
}

// ---------------------------------------------------------------------------
// Kernel 0: pair-pack the 7 weights: g_W2[w][k2*256 + c*2 + p] = W[c][2k2+p]
// ---------------------------------------------------------------------------
__global__ void prep_kernel(const float* __restrict__ Wz, const float* __restrict__ Uz,
                            const float* __restrict__ Wr, const float* __restrict__ Ur,
                            const float* __restrict__ Wh, const float* __restrict__ Uh,
                            const float* __restrict__ Wp) {
    const float* src = (blockIdx.x == 0) ? Wz : (blockIdx.x == 1) ? Uz :
                       (blockIdx.x == 2) ? Wr : (blockIdx.x == 3) ? Ur :
                       (blockIdx.x == 4) ? Wh : (blockIdx.x == 5) ? Uh : Wp;
    float* dst = g_W2 + blockIdx.x * (ND * ND);
    for (int idx = threadIdx.x; idx < ND * ND; idx += blockDim.x) {
        int k2 = idx >> 8, c = (idx >> 1) & 127, p = idx & 1;
        dst[idx] = src[c * ND + 2 * k2 + p];
    }
}

// ---------------------------------------------------------------------------
// Kernel 1 (once): hp0 = init_node @ Wp^T, written pair-packed.
// 256 thr, 64-node tiles (grid 768). W fully resident (two 64-k halves).
// ---------------------------------------------------------------------------
#define XW_SMEM ((64 * 132 + 128 * 128) * 4)   // 99328
__global__ void __launch_bounds__(256) xw_kernel(const float* __restrict__ X) {
    extern __shared__ float sm[];
    float* sX = sm;                 // [64][132]
    float* sW = sm + 64 * 132;      // pair layout, 16384 floats (64 k2-rows)
    int tid = threadIdx.x, wid = tid >> 5, lane = tid & 31;
    int lr = lane >> 2, lc = lane & 3;
    int warpR = wid & 1, warpC = wid >> 1;
    int r0 = warpR * 32 + lr * 4;
    long base = (long)blockIdx.x * 64;
#pragma unroll
    for (int t = 0; t < 8; t++) {
        int f = tid + t * 256; int r = f >> 5, c = (f & 31) << 2;
        cp16(sX + r * 132 + c, X + (base + r) * ND + c);
    }
#pragma unroll
    for (int t = 0; t < 16; t++) {
        int f = tid + t * 256;
        cp16(sW + f * 4, g_W2 + 6 * ND * ND + f * 4);
    }
    CP_COMMIT();
    CP_WAIT(0); __syncthreads();
    ull acc[4][8];
    zacc(acc);
    mma_w<132>(sX, sW, 0, r0, lc, warpC, acc);
    mma_w<132>(sX, sW + 32 * 256, 64, r0, lc, warpC, acc);
#pragma unroll
    for (int i = 0; i < 4; i++) {
        long g = base + r0 + i;
        int b = (int)(g >> 9), j = (int)(g & 511);
        float* dst = g_hp + ((size_t)b * 256 + (j >> 1)) * 256 + (j & 1);
#pragma unroll
        for (int jj = 0; jj < 8; jj++)
            dst[col_of(warpC, lc, jj) * 2] = accval(acc[i][jj]);
    }
}

// ---------------------------------------------------------------------------
// Kernel 2: neigh[b] = mask[b] @ hp[b] + 512*Wp_b. 64-row tiles, grid (8,96),
// 256 thr, K=512 in 8 chunks of 64 j, cp.async double-buffered.
// 100352 B smem -> 2 CTA/SM.
// ---------------------------------------------------------------------------
#define MG_SMEM ((2 * 64 * 68 + 2 * 32 * 256) * 4)   // 100352
__global__ void __launch_bounds__(256) maskgemm_kernel(const float* __restrict__ mask,
                                                       const float* __restrict__ bp) {
    extern __shared__ float sm[];
    float* sA[2] = { sm, sm + 64 * 68 };
    float* sB[2] = { sm + 2 * 64 * 68, sm + 2 * 64 * 68 + 32 * 256 };
    int b = blockIdx.y;
    int row0g = blockIdx.x * 64;
    int tid = threadIdx.x, wid = tid >> 5, lane = tid & 31;
    int lr = lane >> 2, lc = lane & 3;
    int warpR = wid & 1, warpC = wid >> 1;
    int r0 = warpR * 32 + lr * 4;
    const float* mrow = mask + ((size_t)b * NN + row0g) * NN;
    const float* hpb  = g_hp + (size_t)b * 256 * 256;

    float bj[8];
#pragma unroll
    for (int j = 0; j < 8; j++) bj[j] = 512.0f * __ldg(bp + col_of(warpC, lc, j));

    auto loadChunk = [&](int buf, int c) {
#pragma unroll
        for (int t = 0; t < 4; t++) {          // mask 64x64: 1024 f4
            int f = tid + t * 256;
            int r = f >> 4, kq = (f & 15) << 2;
            cp16(sA[buf] + r * 68 + kq, mrow + (size_t)r * NN + c * 64 + kq);
        }
#pragma unroll
        for (int t = 0; t < 8; t++) {          // hp paired chunk: 32 j2 x 256
            int f = tid + t * 256;
            cp16(sB[buf] + f * 4, hpb + (size_t)c * 8192 + f * 4);
        }
        CP_COMMIT();
    };

    ull acc[4][8];
    zacc(acc);
    loadChunk(0, 0);
#pragma unroll 1
    for (int c = 0; c < 8; c++) {
        if (c < 7) { loadChunk((c + 1) & 1, c + 1); CP_WAIT(1); }
        else       { CP_WAIT(0); }
        __syncthreads();
        mma_w<68>(sA[c & 1], sB[c & 1], 0, r0, lc, warpC, acc);
        __syncthreads();
    }
    float* orow = g_neigh + ((size_t)b * NN + row0g) * ND;
#pragma unroll
    for (int i = 0; i < 4; i++) {
        float* r = orow + (size_t)(r0 + i) * ND;
#pragma unroll
        for (int g = 0; g < 4; g++) {
            float2 v;
            v.x = accval(acc[i][g * 2 + 0]) + bj[g * 2 + 0];
            v.y = accval(acc[i][g * 2 + 1]) + bj[g * 2 + 1];
            *(float2*)(r + col_of(warpC, lc, g * 2)) = v;
        }
    }
}

// ---------------------------------------------------------------------------
// Kernel 3: fused GRU, 64 nodes/CTA, half-weight (64-k) ping-pong pipeline.
// smem: sN[64][132] (neigh->h'), sH (h), sRH (r*h), wb0/wb1 [32 k2][256].
// 14 weight-halves streamed: idx = w*2 + half.
// ---------------------------------------------------------------------------
#define GRU_SMEM ((3 * 64 * 132 + 2 * 32 * 256 + 3 * 128) * 4)   // 168448+1536
__global__ void __launch_bounds__(256) gru_kernel(const float* __restrict__ h_in,
                                                  float* __restrict__ h_out,
                                                  const float* __restrict__ Wz_b, const float* __restrict__ Uz_b,
                                                  const float* __restrict__ Wr_b, const float* __restrict__ Ur_b,
                                                  const float* __restrict__ Wh_b, const float* __restrict__ Uh_b,
                                                  int do_hp) {
    extern __shared__ float sm[];
    float* sN  = sm;                        // [64][132]
    float* sH  = sN + 64 * 132;
    float* sRH = sH + 64 * 132;
    float* wb0 = sRH + 64 * 132;            // [32 k2][256]
    float* wb1 = wb0 + 32 * 256;
    float* sBz = wb1 + 32 * 256;            // 128
    float* sBr = sBz + 128;
    float* sBh = sBr + 128;
    float* wb[2] = { wb0, wb1 };
    int tid = threadIdx.x, wid = tid >> 5, lane = tid & 31;
    int lr = lane >> 2, lc = lane & 3;
    int warpR = wid & 1, warpC = wid >> 1;
    int r0 = warpR * 32 + lr * 4;
    long base = (long)blockIdx.x * 64;

    auto pf = [&](int idx) {                 // prefetch weight-half idx; commits
        float* dst = wb[idx & 1];
        const float* src = g_W2 + (idx >> 1) * (ND * ND) + (idx & 1) * 8192;
#pragma unroll
        for (int t = 0; t < 8; t++) {
            int f = tid + t * 256;
            cp16(dst + f * 4, src + f * 4);
        }
        CP_COMMIT();
    };

    // G0 = {sN, sH, half0}; G1 = {half1}
#pragma unroll
    for (int t = 0; t < 8; t++) {
        int f = tid + t * 256; int r = f >> 5, c = (f & 31) << 2;
        cp16(sN + r * 132 + c, g_neigh + (base + r) * ND + c);
        cp16(sH + r * 132 + c, h_in + (base + r) * ND + c);
    }
#pragma unroll
    for (int t = 0; t < 8; t++) {
        int f = tid + t * 256;
        cp16(wb0 + f * 4, g_W2 + f * 4);     // Wz half0
    }
    CP_COMMIT();                             // G0
    pf(1);                                   // G1 = Wz half1
    if (tid < 128) {
        sBz[tid] = Wz_b[tid] + Uz_b[tid];
        sBr[tid] = Wr_b[tid] + Ur_b[tid];
        sBh[tid] = Wh_b[tid] + Uh_b[tid];
    }

    ull acc[4][8];
    float zf[4][8], rh[4][8];

#define GSTEP(idx, Aptr) do { \
        CP_WAIT(1); __syncthreads(); \
        mma_w<132>((Aptr), wb[(idx) & 1], ((idx) & 1) * 64, r0, lc, warpC, acc); \
        __syncthreads(); \
        if ((idx) + 2 < 14) pf((idx) + 2); \
    } while (0)

    // ---- z = sig(neigh@Wz + h@Uz + bz) ----
    zacc(acc);
    GSTEP(0, sN); GSTEP(1, sN); GSTEP(2, sH); GSTEP(3, sH);
#pragma unroll
    for (int i = 0; i < 4; i++)
#pragma unroll
        for (int j = 0; j < 8; j++)
            zf[i][j] = sigmoidf_(accval(acc[i][j]) + sBz[col_of(warpC, lc, j)]);
    // ---- r = sig(neigh@Wr + h@Ur + br); park rh = r*h in regs ----
    zacc(acc);
    GSTEP(4, sN); GSTEP(5, sN); GSTEP(6, sH); GSTEP(7, sH);
#pragma unroll
    for (int i = 0; i < 4; i++)
#pragma unroll
        for (int j = 0; j < 8; j++) {
            int c = col_of(warpC, lc, j);
            float rv = sigmoidf_(accval(acc[i][j]) + sBr[c]);
            rh[i][j] = rv * sH[(r0 + i) * 132 + c];
        }
    // stage rh into sRH (own cells)
#pragma unroll
    for (int i = 0; i < 4; i++)
#pragma unroll
        for (int j = 0; j < 8; j++)
            sRH[(r0 + i) * 132 + col_of(warpC, lc, j)] = rh[i][j];
    // ---- hhat: neigh@Wh then rh@Uh ----
    zacc(acc);
    GSTEP(8, sN); GSTEP(9, sN);              // last sN(neigh) reads
    GSTEP(10, sRH); GSTEP(11, sRH);          // entry syncs fence sRH writes
    // ---- combine: h' = h + z*(tanh(acc+bh) - h); write h_out; stage h' ----
#pragma unroll
    for (int i = 0; i < 4; i++) {
        float* horow = h_out + (base + r0 + i) * ND;
#pragma unroll
        for (int g = 0; g < 4; g++) {
            float2 v;
#pragma unroll
            for (int p = 0; p < 2; p++) {
                int j = g * 2 + p;
                int c = col_of(warpC, lc, j);
                float hh = tanhf(accval(acc[i][j]) + sBh[c]);
                float h = sH[(r0 + i) * 132 + c];
                float hn = fmaf(zf[i][j], hh - h, h);
                sN[(r0 + i) * 132 + c] = hn;             // own cell
                (p == 0) ? (v.x = hn) : (v.y = hn);
            }
            *(float2*)(horow + col_of(warpC, lc, g * 2)) = v;
        }
    }
    if (do_hp) {
        zacc(acc);
        GSTEP(12, sN);                       // Wp half0 (entry sync fences h')
        CP_WAIT(0); __syncthreads();         // Wp half1 (group 13)
        mma_w<132>(sN, wb[1], 64, r0, lc, warpC, acc);
#pragma unroll
        for (int i = 0; i < 4; i++) {
            long g = base + r0 + i;
            int b = (int)(g >> 9), j = (int)(g & 511);
            float* dst = g_hp + ((size_t)b * 256 + (j >> 1)) * 256 + (j & 1);
#pragma unroll
            for (int jj = 0; jj < 8; jj++)
                dst[col_of(warpC, lc, jj) * 2] = accval(acc[i][jj]);
        }
    } else {
        CP_WAIT(0);                          // drain ledger
    }
#undef GSTEP
}

// ---------------------------------------------------------------------------
extern "C" void kernel_launch(void* const* d_in, const int* in_sizes, int n_in,
                              void* d_out, int out_size) {
    const float* init_node = (const float*)d_in[0];
    const float* mask      = (const float*)d_in[1];
    // d_in[2] = n_steps (fixed at 5 by the problem definition)
    const float* Wp_w = (const float*)d_in[3];
    const float* Wp_b = (const float*)d_in[4];
    const float* Wz_w = (const float*)d_in[5];
    const float* Wz_b = (const float*)d_in[6];
    const float* Uz_w = (const float*)d_in[7];
    const float* Uz_b = (const float*)d_in[8];
    const float* Wr_w = (const float*)d_in[9];
    const float* Wr_b = (const float*)d_in[10];
    const float* Ur_w = (const float*)d_in[11];
    const float* Ur_b = (const float*)d_in[12];
    const float* Wh_w = (const float*)d_in[13];
    const float* Wh_b = (const float*)d_in[14];
    const float* Uh_w = (const float*)d_in[15];
    const float* Uh_b = (const float*)d_in[16];
    float* hout = (float*)d_out;

    cudaFuncSetAttribute(gru_kernel,      cudaFuncAttributeMaxDynamicSharedMemorySize, GRU_SMEM);
    cudaFuncSetAttribute(xw_kernel,       cudaFuncAttributeMaxDynamicSharedMemorySize, XW_SMEM);
    cudaFuncSetAttribute(maskgemm_kernel, cudaFuncAttributeMaxDynamicSharedMemorySize, MG_SMEM);

    prep_kernel<<<7, 256>>>(Wz_w, Uz_w, Wr_w, Ur_w, Wh_w, Uh_w, Wp_w);
    xw_kernel<<<NROWS / 64, 256, XW_SMEM>>>(init_node);

    for (int s = 0; s < NSTEPS; s++) {
        maskgemm_kernel<<<dim3(NN / 64, NB), 256, MG_SMEM>>>(mask, Wp_b);
        gru_kernel<<<NROWS / 64, 256, GRU_SMEM>>>(
            (s == 0) ? init_node : hout, hout,
            Wz_b, Uz_b, Wr_b, Ur_b, Wh_b, Uh_b, (s < NSTEPS - 1) ? 1 : 0);
    }
}

// round 17
// speedup vs baseline: 1.0751x; 1.0751x over previous
#include <cuda_runtime.h>
#include <cstdint>

// Problem constants (fixed by setup_inputs): B=96, N_NODE=512, D=128, n_steps=5
#define NB 96
#define NN 512
#define ND 128
#define NROWS (NB * NN)            // 49152
#define NSTEPS 5

// Scratch (allocation-free rule: __device__ globals)
__device__ float g_hp[NROWS * ND];      // h @ Wp^T  [node][feat]
__device__ float g_neigh[NROWS * ND];   // mask @ hp + 512*bp
__device__ float g_z[NROWS * ND];       // z-gate spill (thread-local roundtrip)
__device__ float g_Wt[7 * ND * ND];     // transposed weights: [k][j] = W[j][k]
// order: 0=Wz 1=Uz 2=Wr 3=Ur 4=Wh 5=Uh 6=Wp

typedef unsigned long long ull;

__device__ __forceinline__ ull pack2(float lo, float hi) {
    ull r; asm("mov.b64 %0, {%1,%2};" : "=l"(r) : "f"(lo), "f"(hi)); return r;
}
__device__ __forceinline__ void fma2(ull& d, ull a, ull b) {
    asm("fma.rn.f32x2 %0, %1, %2, %0;" : "+l"(d) : "l"(a), "l"(b));
}
__device__ __forceinline__ void unpack2(ull v, float& lo, float& hi) {
    asm("mov.b64 {%0,%1}, %2;" : "=f"(lo), "=f"(hi) : "l"(v));
}
__device__ __forceinline__ float sigmoidf_(float x) { return 1.0f / (1.0f + __expf(-x)); }
__device__ __forceinline__ uint32_t s2u(const void* p) {
    uint32_t a;
    asm("{ .reg .u64 t; cvta.to.shared.u64 t, %1; cvt.u32.u64 %0, t; }" : "=r"(a) : "l"(p));
    return a;
}
__device__ __forceinline__ void cp16(float* dst, const float* src) {
    asm volatile("cp.async.cg.shared.global [%0], [%1], 16;" :: "r"(s2u(dst)), "l"(src));
}
#define CP_COMMIT() asm volatile("cp.async.commit_group;")
#define CP_WAIT(n)  asm volatile("cp.async.wait_group %0;" :: "n"(n))

// ---------------------------------------------------------------------------
// r8c8 micro-kernel over a 64-k slab: thread computes 8 rows x 8 cols.
// 256 threads = 16x16 (tx,ty): rows r0=8*ty..+7; cols c0=4*tx..+3, c0+64..+67.
// sX: [128 rows][LDA] (k contig), k index = kbase + k.  sW: [64 k][132].
// ---------------------------------------------------------------------------
template <int LDA>
__device__ __forceinline__ void mma_half(const float* __restrict__ sX,
                                         const float* __restrict__ sW,
                                         int kbase, int r0, int c0, ull acc[8][4]) {
#pragma unroll 2
    for (int k = 0; k < 64; k += 4) {
        float4 a[8];
#pragma unroll
        for (int i = 0; i < 8; i++)
            a[i] = *(const float4*)(sX + (r0 + i) * LDA + kbase + k);
#pragma unroll
        for (int kk = 0; kk < 4; kk++) {
            const float* wr = sW + (k + kk) * 132;
            float4 w0 = *(const float4*)(wr + c0);
            float4 w1 = *(const float4*)(wr + c0 + 64);
            ull wp0 = pack2(w0.x, w0.y), wp1 = pack2(w0.z, w0.w);
            ull wp2 = pack2(w1.x, w1.y), wp3 = pack2(w1.z, w1.w);
#pragma unroll
            for (int i = 0; i < 8; i++) {
                float e = (kk == 0) ? a[i].x : (kk == 1) ? a[i].y : (kk == 2) ? a[i].z : a[i].w;
                ull ap = pack2(e, e);
                fma2(acc[i][0], ap, wp0); fma2(acc[i][1], ap, wp1);
                fma2(acc[i][2], ap, wp2); fma2(acc[i][3], ap, wp3);
            }
        }
    }
}

// r8c4 micro-kernel over a 64-k slab for the mask GEMM (64-col tile).
// sX: [128 rows][LDA], sW: [64 k][LDB]. cols c0..c0+3 (c0 = 4*tx).
template <int LDA, int LDB>
__device__ __forceinline__ void mma_c4(const float* __restrict__ sX,
                                       const float* __restrict__ sW,
                                       int r0, int c0, ull acc[8][2]) {
#pragma unroll 2
    for (int k = 0; k < 64; k += 4) {
        float4 a[8];
#pragma unroll
        for (int i = 0; i < 8; i++)
            a[i] = *(const float4*)(sX + (r0 + i) * LDA + k);
#pragma unroll
        for (int kk = 0; kk < 4; kk++) {
            const float* wr = sW + (k + kk) * LDB;
            float4 w = *(const float4*)(wr + c0);
            ull wp0 = pack2(w.x, w.y), wp1 = pack2(w.z, w.w);
#pragma unroll
            for (int i = 0; i < 8; i++) {
                float e = (kk == 0) ? a[i].x : (kk == 1) ? a[i].y : (kk == 2) ? a[i].z : a[i].w;
                ull ap = pack2(e, e);
                fma2(acc[i][0], ap, wp0); fma2(acc[i][1], ap, wp1);
            }
        }
    }
}

__device__ __forceinline__ void zero_acc8(ull acc[8][4]) {
#pragma unroll
    for (int i = 0; i < 8; i++)
#pragma unroll
        for (int p = 0; p < 4; p++) acc[i][p] = 0ull;
}
__device__ __forceinline__ void row_to_f8(const ull a[4], float o[8]) {
    unpack2(a[0], o[0], o[1]); unpack2(a[1], o[2], o[3]);
    unpack2(a[2], o[4], o[5]); unpack2(a[3], o[6], o[7]);
}
__device__ __forceinline__ int colof(int c0, int j) { return (j < 4) ? (c0 + j) : (c0 + 60 + j); }

// Async-load one 64x128 weight half into smem [64][132]; commits a group.
__device__ __forceinline__ void cp_half(float* __restrict__ dst, const float* __restrict__ src) {
#pragma unroll
    for (int t = 0; t < 8; t++) {
        int f = threadIdx.x + t * 256;          // 0..2047 float4s
        int k = f >> 5, c = (f & 31) << 2;
        cp16(dst + k * 132 + c, src + k * 128 + c);
    }
    CP_COMMIT();
}

// ---------------------------------------------------------------------------
// Kernel 1: transpose the 7 weight matrices once into g_Wt
// ---------------------------------------------------------------------------
__global__ void transpose_weights_kernel(const float* __restrict__ Wz, const float* __restrict__ Uz,
                                         const float* __restrict__ Wr, const float* __restrict__ Ur,
                                         const float* __restrict__ Wh, const float* __restrict__ Uh,
                                         const float* __restrict__ Wp) {
    const float* src = (blockIdx.x == 0) ? Wz : (blockIdx.x == 1) ? Uz :
                       (blockIdx.x == 2) ? Wr : (blockIdx.x == 3) ? Ur :
                       (blockIdx.x == 4) ? Wh : (blockIdx.x == 5) ? Uh : Wp;
    float* dst = g_Wt + blockIdx.x * (ND * ND);
    for (int idx = threadIdx.x; idx < ND * ND; idx += blockDim.x) {
        int j = idx >> 7, k = idx & 127;
        dst[k * ND + j] = src[idx];
    }
}

// ---------------------------------------------------------------------------
// Kernel 2: hp0 = init_node @ Wp^T  (one-time). 128-row tiles, r8c8.
// ---------------------------------------------------------------------------
#define XW_SMEM ((128 * 132 * 2) * 4)   // 135168
__global__ void __launch_bounds__(256) xw_kernel(const float* __restrict__ X,
                                                 const float* __restrict__ Wt,
                                                 float* __restrict__ out) {
    extern __shared__ float sm[];
    float* sX = sm;                 // [128][132]
    float* sW = sm + 128 * 132;     // [128][132]
    int tid = threadIdx.x;
    int tx = tid & 15, ty = tid >> 4;
    int c0 = tx * 4, r0 = ty * 8;
    long base = (long)blockIdx.x * 128;
#pragma unroll
    for (int t = 0; t < 16; t++) {
        int f = tid + t * 256;      // 0..4095 f4
        int r = f >> 5, c = (f & 31) << 2;
        *(float4*)(sX + r * 132 + c) = *(const float4*)(X + (base + r) * ND + c);
        *(float4*)(sW + r * 132 + c) = *(const float4*)(Wt + r * 128 + c);
    }
    __syncthreads();
    ull acc[8][4];
    zero_acc8(acc);
    mma_half<132>(sX, sW, 0, r0, c0, acc);
    mma_half<132>(sX, sW + 64 * 132, 64, r0, c0, acc);
#pragma unroll
    for (int i = 0; i < 8; i++) {
        float o[8]; row_to_f8(acc[i], o);
        float* orow = out + (base + r0 + i) * ND;
        *(float4*)(orow + c0)      = make_float4(o[0], o[1], o[2], o[3]);
        *(float4*)(orow + c0 + 64) = make_float4(o[4], o[5], o[6], o[7]);
    }
}

// ---------------------------------------------------------------------------
// Kernel 3: neigh[b] = mask[b] @ hp[b] + 512*Wp_b.
// 128 rows x 64 feat-cols per CTA, grid (4 rowtiles, 2 coltiles, 96),
// r8c4, smem 104448 B -> 2 CTAs/SM (16 resident warps hide chunk stalls).
// Mask tile read by the 2 co-resident coltile CTAs -> L2 hit on 2nd read.
// ---------------------------------------------------------------------------
#define MG_SMEM ((2 * 128 * 68 + 2 * 64 * 68) * 4)   // 104448
__global__ void __launch_bounds__(256) maskgemm_kernel(const float* __restrict__ mask,
                                                       const float* __restrict__ hp,
                                                       const float* __restrict__ bp,
                                                       float* __restrict__ neigh) {
    extern __shared__ float sm[];
    float* sA[2] = { sm, sm + 128 * 68 };
    float* sB[2] = { sm + 2 * 128 * 68, sm + 2 * 128 * 68 + 64 * 68 };
    int b = blockIdx.z;
    int row0g = blockIdx.x * 128;
    int feat0 = blockIdx.y * 64;
    int tid = threadIdx.x;
    int tx = tid & 15, ty = tid >> 4;
    int c0 = tx * 4, r0 = ty * 8;
    const float* mrow = mask + ((size_t)b * NN + row0g) * NN;
    const float* hpb  = hp + (size_t)b * NN * ND + feat0;

    float bj[4];
#pragma unroll
    for (int j = 0; j < 4; j++) bj[j] = 512.0f * __ldg(bp + feat0 + c0 + j);

    auto loadChunk = [&](int buf, int k0) {
#pragma unroll
        for (int t = 0; t < 8; t++) {          // mask 128x64: 2048 f4
            int f = tid + t * 256;
            int r = f >> 4, kq = (f & 15) << 2;
            cp16(sA[buf] + r * 68 + kq, mrow + (size_t)r * NN + k0 + kq);
        }
#pragma unroll
        for (int t = 0; t < 4; t++) {          // hp 64k x 64 cols: 1024 f4
            int f = tid + t * 256;
            int k = f >> 4, c = (f & 15) << 2;
            cp16(sB[buf] + k * 68 + c, hpb + (size_t)(k0 + k) * ND + c);
        }
        CP_COMMIT();
    };

    ull acc[8][2];
#pragma unroll
    for (int i = 0; i < 8; i++) { acc[i][0] = 0ull; acc[i][1] = 0ull; }
    loadChunk(0, 0);
#pragma unroll 1
    for (int c = 0; c < 8; c++) {
        if (c < 7) { loadChunk((c + 1) & 1, (c + 1) * 64); CP_WAIT(1); }
        else       { CP_WAIT(0); }
        __syncthreads();
        mma_c4<68, 68>(sA[c & 1], sB[c & 1], r0, c0, acc);
        __syncthreads();
    }
    float* orow = neigh + ((size_t)b * NN + row0g) * ND + feat0;
#pragma unroll
    for (int i = 0; i < 8; i++) {
        float o0, o1, o2, o3;
        unpack2(acc[i][0], o0, o1);
        unpack2(acc[i][1], o2, o3);
        *(float4*)(orow + (size_t)(r0 + i) * ND + c0) =
            make_float4(o0 + bj[0], o1 + bj[1], o2 + bj[2], o3 + bj[3]);
    }
}

// ---------------------------------------------------------------------------
// Kernel 4: fused GRU (R8 config, unchanged): 128 nodes/CTA, r8c8,
// half-weight ping-pong; z spills through g_z.
// ---------------------------------------------------------------------------
#define GRU_SMEM ((2 * 128 * 132 + 2 * 64 * 132 + 3 * 128) * 4)   // 204288
__global__ void __launch_bounds__(256) gru_kernel(const float* __restrict__ neigh,
                                                  const float* __restrict__ h_in,
                                                  float* __restrict__ h_out,
                                                  float* __restrict__ hp_out,
                                                  float* __restrict__ zbuf,
                                                  const float* __restrict__ Wt,
                                                  const float* __restrict__ Wz_b, const float* __restrict__ Uz_b,
                                                  const float* __restrict__ Wr_b, const float* __restrict__ Ur_b,
                                                  const float* __restrict__ Wh_b, const float* __restrict__ Uh_b,
                                                  int do_hp) {
    extern __shared__ float sm[];
    float* sN  = sm;                       // 128*132
    float* sH  = sm + 128 * 132;           // 128*132
    float* wb0 = sm + 2 * 128 * 132;       // 64*132
    float* wb1 = wb0 + 64 * 132;           // 64*132
    float* sBz = wb1 + 64 * 132;           // 128
    float* sBr = sBz + 128;
    float* sBh = sBr + 128;
    float* wb[2] = { wb0, wb1 };
    int tid = threadIdx.x;
    int tx = tid & 15, ty = tid >> 4;
    int c0 = tx * 4, r0 = ty * 8;
    long base = (long)blockIdx.x * 128;

    // G0 = {sN, sH, half0=Wz0}; G1 = {half1=Wz1}
#pragma unroll
    for (int t = 0; t < 16; t++) {
        int f = tid + t * 256;
        int r = f >> 5, c = (f & 31) << 2;
        cp16(sN + r * 132 + c, neigh + (base + r) * ND + c);
        cp16(sH + r * 132 + c, h_in + (base + r) * ND + c);
    }
#pragma unroll
    for (int t = 0; t < 8; t++) {
        int f = tid + t * 256;
        int k = f >> 5, c = (f & 31) << 2;
        cp16(wb0 + k * 132 + c, Wt + k * 128 + c);      // Wz half0
    }
    CP_COMMIT();                           // G0
    cp_half(wb1, Wt + 64 * 128);           // G1 = Wz half1
    if (tid < 128) {
        sBz[tid] = Wz_b[tid] + Uz_b[tid];
        sBr[tid] = Wr_b[tid] + Ur_b[tid];
        sBh[tid] = Wh_b[tid] + Uh_b[tid];
    }

    ull arrA[8][4], arrB[8][4];
    float* zF = (float*)arrA;              // reg-array alias for parked floats

    // STEP(i): wait half i ready, compute into acc with operand A, prefetch i+2
#define STEPQ(i, Aptr, acc) do { \
        CP_WAIT(1); __syncthreads(); \
        mma_half<132>(Aptr, wb[(i) & 1], ((i) & 1) * 64, r0, c0, acc); \
        __syncthreads(); \
        if ((i) + 2 <= 13) cp_half(wb[(i) & 1], Wt + (((i) + 2) >> 1) * 16384 + (((i) + 2) & 1) * 8192); \
    } while (0)

    // ---- z = sigma(neigh@Wz + h@Uz + bz) ----
    zero_acc8(arrA);
    STEPQ(0, sN, arrA);                    // Wz half0
    STEPQ(1, sN, arrA);                    // Wz half1
    STEPQ(2, sH, arrA);                    // Uz half0
    STEPQ(3, sH, arrA);                    // Uz half1
#pragma unroll
    for (int i = 0; i < 8; i++) {          // z -> global scratch (own cells)
        float o[8]; row_to_f8(arrA[i], o);
        float z0[4], z1[4];
#pragma unroll
        for (int j = 0; j < 8; j++) {
            float zv = sigmoidf_(o[j] + sBz[colof(c0, j)]);
            if (j < 4) z0[j] = zv; else z1[j - 4] = zv;
        }
        float* zr = zbuf + (base + r0 + i) * ND;
        *(float4*)(zr + c0)      = make_float4(z0[0], z0[1], z0[2], z0[3]);
        *(float4*)(zr + c0 + 64) = make_float4(z1[0], z1[1], z1[2], z1[3]);
    }
    // ---- r = sigma(neigh@Wr + h@Ur + br) ----
    zero_acc8(arrA);
    STEPQ(4, sN, arrA);                    // Wr0
    STEPQ(5, sN, arrA);                    // Wr1
    STEPQ(6, sH, arrA);                    // Ur0
    STEPQ(7, sH, arrA);                    // Ur1
    // rh = r * h, parked in arrA as floats (own cells; h from sH)
#pragma unroll
    for (int i = 0; i < 8; i++) {
        float o[8]; row_to_f8(arrA[i], o);
#pragma unroll
        for (int j = 0; j < 8; j++) {
            int col = colof(c0, j);
            float rv = sigmoidf_(o[j] + sBr[col]);
            zF[i * 8 + j] = rv * sH[(r0 + i) * 132 + col];
        }
    }
    // ---- hhat partial: neigh@Wh (last neigh use) ----
    zero_acc8(arrB);
    STEPQ(8, sN, arrB);                    // Wh0
    STEPQ(9, sN, arrB);                    // Wh1
    // write rh into sN (own cells), then reload z into the freed arrA
#pragma unroll
    for (int i = 0; i < 8; i++) {
        sN[(r0 + i) * 132 + c0 + 0] = zF[i * 8 + 0];
        sN[(r0 + i) * 132 + c0 + 1] = zF[i * 8 + 1];
        sN[(r0 + i) * 132 + c0 + 2] = zF[i * 8 + 2];
        sN[(r0 + i) * 132 + c0 + 3] = zF[i * 8 + 3];
        sN[(r0 + i) * 132 + c0 + 64] = zF[i * 8 + 4];
        sN[(r0 + i) * 132 + c0 + 65] = zF[i * 8 + 5];
        sN[(r0 + i) * 132 + c0 + 66] = zF[i * 8 + 6];
        sN[(r0 + i) * 132 + c0 + 67] = zF[i * 8 + 7];
    }
#pragma unroll
    for (int i = 0; i < 8; i++) {          // z reload (L2-hot, own cells)
        const float* zr = zbuf + (base + r0 + i) * ND;
        float4 a = *(const float4*)(zr + c0);
        float4 b2 = *(const float4*)(zr + c0 + 64);
        zF[i * 8 + 0] = a.x; zF[i * 8 + 1] = a.y; zF[i * 8 + 2] = a.z; zF[i * 8 + 3] = a.w;
        zF[i * 8 + 4] = b2.x; zF[i * 8 + 5] = b2.y; zF[i * 8 + 6] = b2.z; zF[i * 8 + 7] = b2.w;
    }
    // ---- hhat += rh@Uh ----  (STEPQ entry sync makes rh visible)
    STEPQ(10, sN, arrB);                   // Uh0
    STEPQ(11, sN, arrB);                   // Uh1
    // ---- combine: h' = h + z*(hhat - h); write h_out, stage h' in sN ----
#pragma unroll
    for (int i = 0; i < 8; i++) {
        float o[8]; row_to_f8(arrB[i], o);
        float hn[8];
#pragma unroll
        for (int j = 0; j < 8; j++) {
            int col = colof(c0, j);
            float hh = tanhf(o[j] + sBh[col]);
            float h = sH[(r0 + i) * 132 + col];
            hn[j] = fmaf(zF[i * 8 + j], hh - h, h);
            sN[(r0 + i) * 132 + col] = hn[j];
        }
        float* orow = h_out + (base + r0 + i) * ND;
        *(float4*)(orow + c0)      = make_float4(hn[0], hn[1], hn[2], hn[3]);
        *(float4*)(orow + c0 + 64) = make_float4(hn[4], hn[5], hn[6], hn[7]);
    }
    if (do_hp) {
        // ---- hp = h' @ Wp^T ----
        zero_acc8(arrA);
        STEPQ(12, sN, arrA);               // Wp0
        CP_WAIT(0); __syncthreads();
        mma_half<132>(sN, wb[1], 64, r0, c0, arrA);     // Wp1 (no prefetch after)
#pragma unroll
        for (int i = 0; i < 8; i++) {
            float o[8]; row_to_f8(arrA[i], o);
            float* orow = hp_out + (base + r0 + i) * ND;
            *(float4*)(orow + c0)      = make_float4(o[0], o[1], o[2], o[3]);
            *(float4*)(orow + c0 + 64) = make_float4(o[4], o[5], o[6], o[7]);
        }
    } else {
        CP_WAIT(0);                        // drain ledger before exit
    }
#undef STEPQ
}

// ---------------------------------------------------------------------------
extern "C" void kernel_launch(void* const* d_in, const int* in_sizes, int n_in,
                              void* d_out, int out_size) {
    const float* init_node = (const float*)d_in[0];
    const float* mask      = (const float*)d_in[1];
    // d_in[2] = n_steps (fixed at 5 by the problem definition)
    const float* Wp_w = (const float*)d_in[3];
    const float* Wp_b = (const float*)d_in[4];
    const float* Wz_w = (const float*)d_in[5];
    const float* Wz_b = (const float*)d_in[6];
    const float* Uz_w = (const float*)d_in[7];
    const float* Uz_b = (const float*)d_in[8];
    const float* Wr_w = (const float*)d_in[9];
    const float* Wr_b = (const float*)d_in[10];
    const float* Ur_w = (const float*)d_in[11];
    const float* Ur_b = (const float*)d_in[12];
    const float* Wh_w = (const float*)d_in[13];
    const float* Wh_b = (const float*)d_in[14];
    const float* Uh_w = (const float*)d_in[15];
    const float* Uh_b = (const float*)d_in[16];
    float* hout = (float*)d_out;

    float *g_hp_p, *g_neigh_p, *g_Wt_p, *g_z_p;
    cudaGetSymbolAddress((void**)&g_hp_p, g_hp);
    cudaGetSymbolAddress((void**)&g_neigh_p, g_neigh);
    cudaGetSymbolAddress((void**)&g_Wt_p, g_Wt);
    cudaGetSymbolAddress((void**)&g_z_p, g_z);

    cudaFuncSetAttribute(gru_kernel,      cudaFuncAttributeMaxDynamicSharedMemorySize, GRU_SMEM);
    cudaFuncSetAttribute(xw_kernel,       cudaFuncAttributeMaxDynamicSharedMemorySize, XW_SMEM);
    cudaFuncSetAttribute(maskgemm_kernel, cudaFuncAttributeMaxDynamicSharedMemorySize, MG_SMEM);

    transpose_weights_kernel<<<7, 256>>>(Wz_w, Uz_w, Wr_w, Ur_w, Wh_w, Uh_w, Wp_w);
    xw_kernel<<<NROWS / 128, 256, XW_SMEM>>>(init_node, g_Wt_p + 6 * ND * ND, g_hp_p);

    for (int s = 0; s < NSTEPS; s++) {
        maskgemm_kernel<<<dim3(NN / 128, 2, NB), 256, MG_SMEM>>>(mask, g_hp_p, Wp_b, g_neigh_p);
        gru_kernel<<<NROWS / 128, 256, GRU_SMEM>>>(
            g_neigh_p, (s == 0) ? init_node : hout, hout, g_hp_p, g_z_p,
            g_Wt_p, Wz_b, Uz_b, Wr_b, Ur_b, Wh_b, Uh_b, (s < NSTEPS - 1) ? 1 : 0);
    }
}